// round 1
// baseline (speedup 1.0000x reference)
#include <cuda_runtime.h>
#include <math.h>

#define Bc 64
#define Wc 16
#define Tc 64
#define Uc 128
#define Sc 20
#define Nc 8
#define INF_ 100000.0f

// ---------------- scratch (device globals; no allocation allowed) ----------------
__device__ float g_qslot[Bc*Wc*Sc*Uc];     // 2,621,440
__device__ float g_qw[Bc*Wc*Sc*Uc];        // 2,621,440
__device__ float g_qslotW1[Bc*Wc*Sc*Uc];   // 2,621,440  (includes +b1)
__device__ float g_qsW[Bc*Wc*Nc*Uc];       // 1,048,576
__device__ float g_h1[(size_t)Bc*Wc*Sc*Nc*Uc]; // 20,971,520 (84 MB)
__device__ float g_logits[Bc*Wc*Sc*Nc];    // 163,840

// ---------------- kernel 1: attention over utterance tokens -> q_slot ----------------
// grid = B*W (1024), block = 256
__global__ __launch_bounds__(256) void qslot_kernel(
    const float* __restrict__ h, const float* __restrict__ c,
    const float* __restrict__ pos, float* __restrict__ qslot)
{
    __shared__ float h_sh[Tc*129];   // padded to kill bank conflicts
    __shared__ float c_sh[Sc*129];
    __shared__ float p_sh[Sc*Tc];

    int bw  = blockIdx.x;
    int tid = threadIdx.x;
    const float* hb = h + (size_t)bw * Tc * Uc;

    for (int i = tid; i < Tc*Uc; i += 256)
        h_sh[(i >> 7) * 129 + (i & 127)] = hb[i];
    for (int i = tid; i < Sc*Uc; i += 256)
        c_sh[(i >> 7) * 129 + (i & 127)] = c[i];
    __syncthreads();

    // p[s][t] = <c[s], h[t]>
    for (int j = tid; j < Sc*Tc; j += 256) {
        int s = j >> 6, t = j & 63;
        const float* cr = c_sh + s * 129;
        const float* hr = h_sh + t * 129;
        float acc = 0.f;
        #pragma unroll
        for (int u = 0; u < Uc; u++) acc = fmaf(cr[u], hr[u], acc);
        p_sh[s*Tc + t] = acc;
    }
    __syncthreads();

    // masked softmax over t (mask: where p==0 add -INF_)
    if (tid < Sc) {
        float* pr = p_sh + tid * Tc;
        float m = -3.4e38f;
        #pragma unroll
        for (int t = 0; t < Tc; t++) {
            float v = pr[t];
            if (v == 0.f) v = -INF_;
            pr[t] = v;
            m = fmaxf(m, v);
        }
        float sum = 0.f;
        #pragma unroll
        for (int t = 0; t < Tc; t++) { float e = expf(pr[t] - m); pr[t] = e; sum += e; }
        float r = 1.f / sum;
        #pragma unroll
        for (int t = 0; t < Tc; t++) pr[t] *= r;
    }
    __syncthreads();

    // q_slot[s][u] = sum_t p[s][t] h[t][u] + pos
    const float* posb = pos + (size_t)bw * Sc * Uc;
    float* qb = qslot + (size_t)bw * Sc * Uc;
    for (int j = tid; j < Sc*Uc; j += 256) {
        int s = j >> 7, u = j & 127;
        const float* pr = p_sh + s * Tc;
        float acc = 0.f;
        #pragma unroll
        for (int t = 0; t < Tc; t++) acc = fmaf(pr[t], h_sh[t*129 + u], acc);
        qb[j] = acc + posb[j];
    }
}

// ---------------- kernel 2: generic C[M,128] = A[M,128] @ Wm[128,128] (+bias) ----------------
// grid = M/32, block = 256, each thread 4x4 register tile
__global__ __launch_bounds__(256) void gemm128_kernel(
    const float* __restrict__ A, const float* __restrict__ Wm,
    const float* __restrict__ bias, float* __restrict__ C, int M)
{
    __shared__ float A_sh[32*33];
    __shared__ float W_sh[32*128];
    int tid  = threadIdx.x;
    int row0 = blockIdx.x * 32;
    int tx = tid & 31, ty = tid >> 5;
    int r0 = ty * 4, c0 = tx * 4;
    float acc[4][4] = {};

    for (int k0 = 0; k0 < 128; k0 += 32) {
        // A tile transposed into shared (k-major)
        #pragma unroll
        for (int rr = 0; rr < 32; rr += 8) {
            int r = rr + ty;
            A_sh[tx*33 + r] = A[(size_t)(row0 + r) * 128 + k0 + tx];
        }
        for (int i = tid; i < 32*128; i += 256)
            W_sh[i] = Wm[(size_t)(k0 + (i >> 7)) * 128 + (i & 127)];
        __syncthreads();
        #pragma unroll
        for (int k = 0; k < 32; k++) {
            float4 w = *(const float4*)&W_sh[k*128 + c0];
            float a0 = A_sh[k*33 + r0 + 0];
            float a1 = A_sh[k*33 + r0 + 1];
            float a2 = A_sh[k*33 + r0 + 2];
            float a3 = A_sh[k*33 + r0 + 3];
            acc[0][0] = fmaf(a0, w.x, acc[0][0]); acc[0][1] = fmaf(a0, w.y, acc[0][1]);
            acc[0][2] = fmaf(a0, w.z, acc[0][2]); acc[0][3] = fmaf(a0, w.w, acc[0][3]);
            acc[1][0] = fmaf(a1, w.x, acc[1][0]); acc[1][1] = fmaf(a1, w.y, acc[1][1]);
            acc[1][2] = fmaf(a1, w.z, acc[1][2]); acc[1][3] = fmaf(a1, w.w, acc[1][3]);
            acc[2][0] = fmaf(a2, w.x, acc[2][0]); acc[2][1] = fmaf(a2, w.y, acc[2][1]);
            acc[2][2] = fmaf(a2, w.z, acc[2][2]); acc[2][3] = fmaf(a2, w.w, acc[2][3]);
            acc[3][0] = fmaf(a3, w.x, acc[3][0]); acc[3][1] = fmaf(a3, w.y, acc[3][1]);
            acc[3][2] = fmaf(a3, w.z, acc[3][2]); acc[3][3] = fmaf(a3, w.w, acc[3][3]);
        }
        __syncthreads();
    }
    float bb0 = bias ? bias[c0+0] : 0.f;
    float bb1 = bias ? bias[c0+1] : 0.f;
    float bb2 = bias ? bias[c0+2] : 0.f;
    float bb3 = bias ? bias[c0+3] : 0.f;
    #pragma unroll
    for (int rr = 0; rr < 4; rr++) {
        float4 o;
        o.x = acc[rr][0] + bb0; o.y = acc[rr][1] + bb1;
        o.z = acc[rr][2] + bb2; o.w = acc[rr][3] + bb3;
        *(float4*)&C[(size_t)(row0 + r0 + rr) * 128 + c0] = o;
    }
}

// ---------------- kernel 3: co-attention softmax over x + layer-1 weighted sum ----------------
// grid = B*W*S (20480), block = 128
__global__ __launch_bounds__(128) void coattn_kernel(
    const float* __restrict__ qw, const float* __restrict__ qstatus,
    const float* __restrict__ qsw, const float* __restrict__ qslotw1,
    float* __restrict__ h1)
{
    __shared__ float tile[8*8*129];  // 33 KB, padded
    __shared__ float co_sh[16*8];
    __shared__ float p2_sh[16*8];
    __shared__ float qwv_sh[128];

    int blk = blockIdx.x;            // b*W*S + w*S + s
    int tid = threadIdx.x;           // 128
    int b = blk / (Wc*Sc);

    qwv_sh[tid] = qw[(size_t)blk * 128 + tid];

    float acc[Nc];
    #pragma unroll
    for (int n = 0; n < Nc; n++) acc[n] = 0.f;

    const float* qs_b = qstatus + (size_t)b * Wc * Nc * Uc;

    // co[x][n] = <qw_row, q_status[b,x,n,:]>  (two x-halves of 8)
    for (int half = 0; half < 2; half++) {
        __syncthreads();
        const float* src = qs_b + (size_t)half * 8 * Nc * Uc;
        for (int i = tid; i < 8*8*128; i += 128)
            tile[(i >> 7) * 129 + (i & 127)] = src[i];
        __syncthreads();
        if (tid < 64) {
            const float* tr = tile + tid * 129;
            float a = 0.f;
            #pragma unroll
            for (int v = 0; v < Uc; v++) a = fmaf(qwv_sh[v], tr[v], a);
            co_sh[half*64 + tid] = a;
        }
    }
    __syncthreads();

    // masked softmax over x (axis of 16) per n
    if (tid < Nc) {
        float vals[16];
        float m = -3.4e38f;
        #pragma unroll
        for (int x = 0; x < 16; x++) {
            float v = co_sh[x*8 + tid];
            if (v == 0.f) v = -INF_;
            vals[x] = v;
            m = fmaxf(m, v);
        }
        float sum = 0.f;
        #pragma unroll
        for (int x = 0; x < 16; x++) { float e = expf(vals[x] - m); vals[x] = e; sum += e; }
        float r = 1.f / sum;
        #pragma unroll
        for (int x = 0; x < 16; x++) p2_sh[x*8 + tid] = vals[x] * r;
    }

    // h1_part[n][v] = sum_x p2[x][n] * qsW[b,x,n,v]
    const float* qsw_b = qsw + (size_t)b * Wc * Nc * Uc;
    for (int half = 0; half < 2; half++) {
        __syncthreads();
        const float* src = qsw_b + (size_t)half * 8 * Nc * Uc;
        for (int i = tid; i < 8*8*128; i += 128)
            tile[(i >> 7) * 129 + (i & 127)] = src[i];
        __syncthreads();
        #pragma unroll
        for (int xl = 0; xl < 8; xl++) {
            int x = half*8 + xl;
            #pragma unroll
            for (int n = 0; n < Nc; n++)
                acc[n] = fmaf(p2_sh[x*8 + n], tile[(xl*8 + n)*129 + tid], acc[n]);
        }
    }

    float base = qslotw1[(size_t)blk * 128 + tid];   // already has +b1
    float* out = h1 + (size_t)blk * Nc * Uc;
    #pragma unroll
    for (int n = 0; n < Nc; n++)
        out[n*128 + tid] = fmaxf(acc[n] + base, 0.f);
}

// ---------------- kernel 4: layer2 GEMM + relu + W3 dot fused ----------------
// grid = (B*W*S*N)/32 = 5120, block = 256
__global__ __launch_bounds__(256) void mlp2_kernel(
    const float* __restrict__ h1, const float* __restrict__ W2,
    const float* __restrict__ b2, const float* __restrict__ W3,
    const float* __restrict__ b3, float* __restrict__ logits)
{
    __shared__ float A_sh[32*33];
    __shared__ float W_sh[32*128];
    int tid  = threadIdx.x;
    int row0 = blockIdx.x * 32;
    int tx = tid & 31, ty = tid >> 5;
    int r0 = ty * 4, c0 = tx * 4;
    float acc[4][4] = {};

    for (int k0 = 0; k0 < 128; k0 += 32) {
        #pragma unroll
        for (int rr = 0; rr < 32; rr += 8) {
            int r = rr + ty;
            A_sh[tx*33 + r] = h1[(size_t)(row0 + r) * 128 + k0 + tx];
        }
        for (int i = tid; i < 32*128; i += 256)
            W_sh[i] = W2[(size_t)(k0 + (i >> 7)) * 128 + (i & 127)];
        __syncthreads();
        #pragma unroll
        for (int k = 0; k < 32; k++) {
            float4 w = *(const float4*)&W_sh[k*128 + c0];
            float a0 = A_sh[k*33 + r0 + 0];
            float a1 = A_sh[k*33 + r0 + 1];
            float a2 = A_sh[k*33 + r0 + 2];
            float a3 = A_sh[k*33 + r0 + 3];
            acc[0][0] = fmaf(a0, w.x, acc[0][0]); acc[0][1] = fmaf(a0, w.y, acc[0][1]);
            acc[0][2] = fmaf(a0, w.z, acc[0][2]); acc[0][3] = fmaf(a0, w.w, acc[0][3]);
            acc[1][0] = fmaf(a1, w.x, acc[1][0]); acc[1][1] = fmaf(a1, w.y, acc[1][1]);
            acc[1][2] = fmaf(a1, w.z, acc[1][2]); acc[1][3] = fmaf(a1, w.w, acc[1][3]);
            acc[2][0] = fmaf(a2, w.x, acc[2][0]); acc[2][1] = fmaf(a2, w.y, acc[2][1]);
            acc[2][2] = fmaf(a2, w.z, acc[2][2]); acc[2][3] = fmaf(a2, w.w, acc[2][3]);
            acc[3][0] = fmaf(a3, w.x, acc[3][0]); acc[3][1] = fmaf(a3, w.y, acc[3][1]);
            acc[3][2] = fmaf(a3, w.z, acc[3][2]); acc[3][3] = fmaf(a3, w.w, acc[3][3]);
        }
        __syncthreads();
    }

    // epilogue: h2 = relu(acc + b2), partial logit = h2 . W3, reduce over 32 lanes
    float w3v[4] = {W3[c0+0], W3[c0+1], W3[c0+2], W3[c0+3]};
    float bbv[4] = {b2[c0+0], b2[c0+1], b2[c0+2], b2[c0+3]};
    float part[4];
    #pragma unroll
    for (int rr = 0; rr < 4; rr++) {
        float p = 0.f;
        #pragma unroll
        for (int cc = 0; cc < 4; cc++) {
            float hv = fmaxf(acc[rr][cc] + bbv[cc], 0.f);
            p = fmaf(hv, w3v[cc], p);
        }
        part[rr] = p;
    }
    #pragma unroll
    for (int off = 16; off > 0; off >>= 1) {
        #pragma unroll
        for (int rr = 0; rr < 4; rr++)
            part[rr] += __shfl_down_sync(0xffffffffu, part[rr], off);
    }
    if (tx == 0) {
        float b3v = b3[0];
        #pragma unroll
        for (int rr = 0; rr < 4; rr++)
            logits[row0 + r0 + rr] = part[rr] + b3v;
    }
}

// ---------------- kernel 5: masked max-pool over W + labels + output packing ----------------
// grid = B (64), block = 160
__global__ __launch_bounds__(160) void finalize_kernel(
    const float* __restrict__ logits, const float* __restrict__ mask,
    float* __restrict__ out, int scalar_idx, int logits_off)
{
    int b = blockIdx.x;
    int k = threadIdx.x; // s*N + n in [0,160)
    float m = -3.4e38f;
    #pragma unroll
    for (int w = 0; w < Wc; w++) {
        size_t idx = (size_t)(b*Wc + w) * (Sc*Nc) + k;
        float v = logits[idx] + mask[idx];
        m = fmaxf(m, v);
    }
    out[b*(Sc*Nc) + k] = (m > 0.f) ? 1.f : 0.f;
    out[(size_t)logits_off + b*(Sc*Nc) + k] = m;
    if (b == 0 && k == 0 && scalar_idx >= 0) out[scalar_idx] = 160.0f;
}

// ---------------- host launcher ----------------
extern "C" void kernel_launch(void* const* d_in, const int* in_sizes, int n_in,
                              void* d_out, int out_size)
{
    const float* h    = (const float*)d_in[0];   // [B,W,T,U]
    const float* c    = (const float*)d_in[1];   // [S,U]
    // d_in[2] status_candidate_c: unused by the reference
    const float* pos  = (const float*)d_in[3];   // [B,W,S,U]
    const float* qst  = (const float*)d_in[4];   // [B,W,N,U]
    const float* mask = (const float*)d_in[5];   // [B,W,S*N]
    const float* wgt  = (const float*)d_in[6];   // [U,U]
    const float* W1   = (const float*)d_in[7];   // [2U,U]
    const float* b1   = (const float*)d_in[8];   // [U]
    const float* W2   = (const float*)d_in[9];   // [U,U]
    const float* b2   = (const float*)d_in[10];  // [U]
    const float* W3   = (const float*)d_in[11];  // [U,1]
    const float* b3   = (const float*)d_in[12];  // [1]
    float* out = (float*)d_out;

    float *qslot_p, *qw_p, *qslotw1_p, *qsw_p, *h1_p, *logits_p;
    cudaGetSymbolAddress((void**)&qslot_p,   g_qslot);
    cudaGetSymbolAddress((void**)&qw_p,      g_qw);
    cudaGetSymbolAddress((void**)&qslotw1_p, g_qslotW1);
    cudaGetSymbolAddress((void**)&qsw_p,     g_qsW);
    cudaGetSymbolAddress((void**)&h1_p,      g_h1);
    cudaGetSymbolAddress((void**)&logits_p,  g_logits);

    const int M_qs  = Bc*Wc*Sc;      // 20480
    const int M_st  = Bc*Wc*Nc;      // 8192
    const int M_mlp = Bc*Wc*Sc*Nc;   // 163840

    // 1. q_slot
    qslot_kernel<<<Bc*Wc, 256>>>(h, c, pos, qslot_p);
    // 2. qw = q_slot @ weight
    gemm128_kernel<<<M_qs/32, 256>>>(qslot_p, wgt, nullptr, qw_p, M_qs);
    // 3. qslotW1 = q_slot @ W1_top + b1
    gemm128_kernel<<<M_qs/32, 256>>>(qslot_p, W1, b1, qslotw1_p, M_qs);
    // 4. qsW = q_status @ W1_bot
    gemm128_kernel<<<M_st/32, 256>>>(qst, W1 + 128*128, nullptr, qsw_p, M_st);
    // 5. co-attention softmax + layer-1
    coattn_kernel<<<Bc*Wc*Sc, 128>>>(qw_p, qst, qsw_p, qslotw1_p, h1_p);
    // 6. layer-2 + layer-3 fused
    mlp2_kernel<<<M_mlp/32, 256>>>(h1_p, W2, b2, W3, b3, logits_p);
    // 7. finalize: output tuple is (labels[B,160], 160, logits[B,160]) flattened
    int scalar_idx = (out_size == 2*Bc*Sc*Nc + 1) ? Bc*Sc*Nc : -1;
    int logits_off = out_size - Bc*Sc*Nc;
    finalize_kernel<<<Bc, 160>>>(logits_p, mask, out, scalar_idx, logits_off);
}

// round 2
// speedup vs baseline: 1.9676x; 1.9676x over previous
#include <cuda_runtime.h>
#include <math.h>

#define Bc 64
#define Wc 16
#define Tc 64
#define Uc 128
#define Sc 20
#define Nc 8
#define INF_ 100000.0f

// ---------------- scratch (device globals; no allocation allowed) ----------------
__device__ float g_qslot[Bc*Wc*Sc*Uc];     // q_slot
__device__ float g_qw[Bc*Wc*Sc*Uc];        // q_slot @ weight
__device__ float g_qslotW1[Bc*Wc*Sc*Uc];   // q_slot @ W1_top + b1
__device__ float g_qsW[Bc*Wc*Nc*Uc];       // q_status @ W1_bot
__device__ float g_logits[Bc*Wc*Sc*Nc];

// packed f32x2 FMA (sm_100+; ptxas never auto-fuses this)
__device__ __forceinline__ float2 ffma2(float2 a, float2 b, float2 c) {
    unsigned long long ua = *reinterpret_cast<unsigned long long*>(&a);
    unsigned long long ub = *reinterpret_cast<unsigned long long*>(&b);
    unsigned long long uc = *reinterpret_cast<unsigned long long*>(&c);
    unsigned long long ud;
    asm("fma.rn.f32x2 %0, %1, %2, %3;" : "=l"(ud) : "l"(ua), "l"(ub), "l"(uc));
    return *reinterpret_cast<float2*>(&ud);
}

// ---------------- kernel 1: attention over utterance tokens -> q_slot ----------------
__global__ __launch_bounds__(256) void qslot_kernel(
    const float* __restrict__ h, const float* __restrict__ c,
    const float* __restrict__ pos, float* __restrict__ qslot)
{
    __shared__ float h_sh[Tc*129];
    __shared__ float c_sh[Sc*129];
    __shared__ float p_sh[Sc*Tc];

    int bw  = blockIdx.x;
    int tid = threadIdx.x;
    const float* hb = h + (size_t)bw * Tc * Uc;

    for (int i = tid; i < Tc*Uc; i += 256)
        h_sh[(i >> 7) * 129 + (i & 127)] = hb[i];
    for (int i = tid; i < Sc*Uc; i += 256)
        c_sh[(i >> 7) * 129 + (i & 127)] = c[i];
    __syncthreads();

    for (int j = tid; j < Sc*Tc; j += 256) {
        int s = j >> 6, t = j & 63;
        const float* cr = c_sh + s * 129;
        const float* hr = h_sh + t * 129;
        float acc = 0.f;
        #pragma unroll
        for (int u = 0; u < Uc; u++) acc = fmaf(cr[u], hr[u], acc);
        p_sh[s*Tc + t] = acc;
    }
    __syncthreads();

    if (tid < Sc) {
        float* pr = p_sh + tid * Tc;
        float m = -3.4e38f;
        #pragma unroll
        for (int t = 0; t < Tc; t++) {
            float v = pr[t];
            if (v == 0.f) v = -INF_;
            pr[t] = v;
            m = fmaxf(m, v);
        }
        float sum = 0.f;
        #pragma unroll
        for (int t = 0; t < Tc; t++) { float e = expf(pr[t] - m); pr[t] = e; sum += e; }
        float r = 1.f / sum;
        #pragma unroll
        for (int t = 0; t < Tc; t++) pr[t] *= r;
    }
    __syncthreads();

    const float* posb = pos + (size_t)bw * Sc * Uc;
    float* qb = qslot + (size_t)bw * Sc * Uc;
    for (int j = tid; j < Sc*Uc; j += 256) {
        int s = j >> 7, u = j & 127;
        const float* pr = p_sh + s * Tc;
        float acc = 0.f;
        #pragma unroll
        for (int t = 0; t < Tc; t++) acc = fmaf(pr[t], h_sh[t*129 + u], acc);
        qb[j] = acc + posb[j];
    }
}

// ---------------- kernel 2: C[M,128] = A[M,128] @ Wm[128,128] (+bias) ----------------
__global__ __launch_bounds__(256) void gemm128_kernel(
    const float* __restrict__ A, const float* __restrict__ Wm,
    const float* __restrict__ bias, float* __restrict__ C, int M)
{
    __shared__ float A_sh[32*33];
    __shared__ float W_sh[32*128];
    int tid  = threadIdx.x;
    int row0 = blockIdx.x * 32;
    int tx = tid & 31, ty = tid >> 5;
    int r0 = ty * 4, c0 = tx * 4;
    float2 acc[4][2] = {};

    for (int k0 = 0; k0 < 128; k0 += 32) {
        #pragma unroll
        for (int rr = 0; rr < 32; rr += 8) {
            int r = rr + ty;
            A_sh[tx*33 + r] = A[(size_t)(row0 + r) * 128 + k0 + tx];
        }
        for (int i = tid; i < 32*128; i += 256)
            W_sh[i] = Wm[(size_t)(k0 + (i >> 7)) * 128 + (i & 127)];
        __syncthreads();
        #pragma unroll
        for (int k = 0; k < 32; k++) {
            float4 w = *(const float4*)&W_sh[k*128 + c0];
            float2 wl = make_float2(w.x, w.y);
            float2 wh = make_float2(w.z, w.w);
            #pragma unroll
            for (int rr = 0; rr < 4; rr++) {
                float a = A_sh[k*33 + r0 + rr];
                float2 aa = make_float2(a, a);
                acc[rr][0] = ffma2(aa, wl, acc[rr][0]);
                acc[rr][1] = ffma2(aa, wh, acc[rr][1]);
            }
        }
        __syncthreads();
    }
    float bb0 = bias ? bias[c0+0] : 0.f;
    float bb1 = bias ? bias[c0+1] : 0.f;
    float bb2 = bias ? bias[c0+2] : 0.f;
    float bb3 = bias ? bias[c0+3] : 0.f;
    #pragma unroll
    for (int rr = 0; rr < 4; rr++) {
        float4 o;
        o.x = acc[rr][0].x + bb0; o.y = acc[rr][0].y + bb1;
        o.z = acc[rr][1].x + bb2; o.w = acc[rr][1].y + bb3;
        *(float4*)&C[(size_t)(row0 + r0 + rr) * 128 + c0] = o;
    }
}

// ---------------- fused kernel: co-attention + softmax + layer1 + layer2 + layer3 ----------------
// grid = B*W (1024), block = 512, dynamic smem 181760 B
// smem layout (floats):
//   [0      , 16384) W2_sh        128x128
//   [16384  , 37504) h1_sh        160 rows x pitch 132  (first 10240 aliased as co_part[4][20][128])
//   [37504  , 40064) qw_sh        20x128
//   [40064  , 42624) q1_sh        20x128 (qslotW1 rows, includes +b1)
//   [42624  , 45184) p2_sh        [s][x][n] 20x16x8 (co in-place -> softmax)
//   [45184  , 45440) bw_sh        b2[128] then W3[128]
#define SM_W2   0
#define SM_H1   16384
#define SM_QW   37504
#define SM_Q1   40064
#define SM_P2   42624
#define SM_BW   45184
#define SM_TOT  45440
#define H1_PITCH 132

__global__ __launch_bounds__(512) void fused_kernel(
    const float* __restrict__ qw, const float* __restrict__ q1,
    const float* __restrict__ qstatus, const float* __restrict__ qsw,
    const float* __restrict__ W2, const float* __restrict__ b2,
    const float* __restrict__ W3, const float* __restrict__ b3,
    float* __restrict__ logits)
{
    extern __shared__ float sm[];
    float* W2_sh = sm + SM_W2;
    float* h1_sh = sm + SM_H1;
    float* co_part = sm + SM_H1;   // alias, dead before h1 written
    float* qw_sh = sm + SM_QW;
    float* q1_sh = sm + SM_Q1;
    float* p2_sh = sm + SM_P2;
    float* bw_sh = sm + SM_BW;

    int bw = blockIdx.x;
    int b  = bw >> 4;
    int tid = threadIdx.x;

    // ---- stage loads ----
    for (int i = tid; i < 16384; i += 512) W2_sh[i] = W2[i];
    for (int i = tid; i < 2560; i += 512) {
        qw_sh[i] = qw[(size_t)bw * 2560 + i];
        q1_sh[i] = q1[(size_t)bw * 2560 + i];
    }
    if (tid < 128) bw_sh[tid] = b2[tid];
    else if (tid < 256) bw_sh[tid] = W3[tid - 128];
    __syncthreads();

    // ---- co[s][x][n] = <qw[s], q_status[b,x,n]> ; u split 4 ways across z ----
    {
        int z = tid >> 7;          // 0..3 -> u-range z*32..z*32+31
        int r = tid & 127;         // r = x*8+n
        float2 acc[Sc];
        #pragma unroll
        for (int s = 0; s < Sc; s++) acc[s] = make_float2(0.f, 0.f);

        const float* qsrow = qstatus + ((size_t)b * 128 + r) * 128 + z * 32;
        #pragma unroll
        for (int cu = 0; cu < 32; cu += 8) {
            float4 qa = *(const float4*)(qsrow + cu);
            float4 qb4 = *(const float4*)(qsrow + cu + 4);
            float2 qp0 = make_float2(qa.x, qa.y);
            float2 qp1 = make_float2(qa.z, qa.w);
            float2 qp2 = make_float2(qb4.x, qb4.y);
            float2 qp3 = make_float2(qb4.z, qb4.w);
            #pragma unroll
            for (int s = 0; s < Sc; s++) {
                const float2* wp = (const float2*)(qw_sh + s * 128 + z * 32 + cu);
                acc[s] = ffma2(qp0, wp[0], acc[s]);
                acc[s] = ffma2(qp1, wp[1], acc[s]);
                acc[s] = ffma2(qp2, wp[2], acc[s]);
                acc[s] = ffma2(qp3, wp[3], acc[s]);
            }
        }
        #pragma unroll
        for (int s = 0; s < Sc; s++)
            co_part[(z * Sc + s) * 128 + r] = acc[s].x + acc[s].y;
    }
    __syncthreads();

    // ---- masked softmax over x (16) per (s,n): 160 threads ----
    if (tid < Sc * Nc) {
        int s = tid >> 3, n = tid & 7;
        float vals[16];
        float m = -3.4e38f;
        #pragma unroll
        for (int x = 0; x < 16; x++) {
            int r = x * 8 + n;
            float v = co_part[(0 * Sc + s) * 128 + r]
                    + co_part[(1 * Sc + s) * 128 + r]
                    + co_part[(2 * Sc + s) * 128 + r]
                    + co_part[(3 * Sc + s) * 128 + r];
            if (v == 0.f) v = -INF_;
            vals[x] = v;
            m = fmaxf(m, v);
        }
        float sum = 0.f;
        #pragma unroll
        for (int x = 0; x < 16; x++) { float e = expf(vals[x] - m); vals[x] = e; sum += e; }
        float rs = 1.f / sum;
        #pragma unroll
        for (int x = 0; x < 16; x++)
            p2_sh[(s * 16 + x) * 8 + n] = vals[x] * rs;
    }
    __syncthreads();

    // ---- layer1: h1[s,n,:] = relu( sum_x p2[s,x,n]*qsW[b,x,n,:] + q1[s,:] ) ----
    {
        int n  = tid >> 6;         // 0..7
        int u2 = tid & 63;         // float2 index
        float2 hacc[Sc];
        #pragma unroll
        for (int s = 0; s < Sc; s++) hacc[s] = make_float2(0.f, 0.f);

        const float* qswb = qsw + (size_t)b * Wc * Nc * Uc;
        #pragma unroll
        for (int x = 0; x < 16; x++) {
            float2 qv = *(const float2*)(qswb + ((size_t)(x * 8 + n)) * 128 + 2 * u2);
            #pragma unroll
            for (int s = 0; s < Sc; s++) {
                float p = p2_sh[(s * 16 + x) * 8 + n];
                hacc[s] = ffma2(make_float2(p, p), qv, hacc[s]);
            }
        }
        __syncthreads();   // co_part reads fully done before h1 overwrite
        #pragma unroll
        for (int s = 0; s < Sc; s++) {
            float2 base = *(const float2*)(q1_sh + s * 128 + 2 * u2);
            float2 hv;
            hv.x = fmaxf(hacc[s].x + base.x, 0.f);
            hv.y = fmaxf(hacc[s].y + base.y, 0.f);
            *(float2*)(h1_sh + (size_t)(s * 8 + n) * H1_PITCH + 2 * u2) = hv;
        }
    }
    __syncthreads();

    // ---- layer2 GEMM [160x128] @ W2[128x128], relu(+b2), dot W3, logits ----
    {
        int tx = tid & 15;         // 8 cols = 4 float2
        int ty = tid >> 4;         // 0..31, rows ty, 32+ty, ... (5 rows)
        int c0 = tx * 8;
        float2 acc2[5][4];
        #pragma unroll
        for (int rr = 0; rr < 5; rr++)
            #pragma unroll
            for (int j = 0; j < 4; j++) acc2[rr][j] = make_float2(0.f, 0.f);

        for (int k = 0; k < 128; k++) {
            float4 w0 = *(const float4*)(W2_sh + k * 128 + c0);
            float4 w1 = *(const float4*)(W2_sh + k * 128 + c0 + 4);
            float2 wp0 = make_float2(w0.x, w0.y);
            float2 wp1 = make_float2(w0.z, w0.w);
            float2 wp2 = make_float2(w1.x, w1.y);
            float2 wp3 = make_float2(w1.z, w1.w);
            #pragma unroll
            for (int rr = 0; rr < 5; rr++) {
                float a = h1_sh[(size_t)(rr * 32 + ty) * H1_PITCH + k];
                float2 aa = make_float2(a, a);
                acc2[rr][0] = ffma2(aa, wp0, acc2[rr][0]);
                acc2[rr][1] = ffma2(aa, wp1, acc2[rr][1]);
                acc2[rr][2] = ffma2(aa, wp2, acc2[rr][2]);
                acc2[rr][3] = ffma2(aa, wp3, acc2[rr][3]);
            }
        }

        float bb[8], w3v[8];
        #pragma unroll
        for (int c = 0; c < 8; c++) {
            bb[c]  = bw_sh[c0 + c];
            w3v[c] = bw_sh[128 + c0 + c];
        }
        float b3v = b3[0];
        #pragma unroll
        for (int rr = 0; rr < 5; rr++) {
            float part = 0.f;
            #pragma unroll
            for (int j = 0; j < 4; j++) {
                float hx = fmaxf(acc2[rr][j].x + bb[2*j],   0.f);
                float hy = fmaxf(acc2[rr][j].y + bb[2*j+1], 0.f);
                part = fmaf(hx, w3v[2*j], part);
                part = fmaf(hy, w3v[2*j+1], part);
            }
            #pragma unroll
            for (int off = 8; off > 0; off >>= 1)
                part += __shfl_down_sync(0xffffffffu, part, off, 16);
            if (tx == 0)
                logits[(size_t)bw * 160 + rr * 32 + ty] = part + b3v;
        }
    }
}

// ---------------- finalize: masked max-pool over W + labels + packing ----------------
__global__ __launch_bounds__(160) void finalize_kernel(
    const float* __restrict__ logits, const float* __restrict__ mask,
    float* __restrict__ out, int scalar_idx, int logits_off)
{
    int b = blockIdx.x;
    int k = threadIdx.x;
    float m = -3.4e38f;
    #pragma unroll
    for (int w = 0; w < Wc; w++) {
        size_t idx = (size_t)(b*Wc + w) * (Sc*Nc) + k;
        float v = logits[idx] + mask[idx];
        m = fmaxf(m, v);
    }
    out[b*(Sc*Nc) + k] = (m > 0.f) ? 1.f : 0.f;
    out[(size_t)logits_off + b*(Sc*Nc) + k] = m;
    if (b == 0 && k == 0 && scalar_idx >= 0) out[scalar_idx] = 160.0f;
}

// ---------------- host launcher ----------------
extern "C" void kernel_launch(void* const* d_in, const int* in_sizes, int n_in,
                              void* d_out, int out_size)
{
    const float* h    = (const float*)d_in[0];
    const float* c    = (const float*)d_in[1];
    const float* pos  = (const float*)d_in[3];
    const float* qst  = (const float*)d_in[4];
    const float* mask = (const float*)d_in[5];
    const float* wgt  = (const float*)d_in[6];
    const float* W1   = (const float*)d_in[7];
    const float* b1   = (const float*)d_in[8];
    const float* W2   = (const float*)d_in[9];
    const float* b2   = (const float*)d_in[10];
    const float* W3   = (const float*)d_in[11];
    const float* b3   = (const float*)d_in[12];
    float* out = (float*)d_out;

    float *qslot_p, *qw_p, *qslotw1_p, *qsw_p, *logits_p;
    cudaGetSymbolAddress((void**)&qslot_p,   g_qslot);
    cudaGetSymbolAddress((void**)&qw_p,      g_qw);
    cudaGetSymbolAddress((void**)&qslotw1_p, g_qslotW1);
    cudaGetSymbolAddress((void**)&qsw_p,     g_qsW);
    cudaGetSymbolAddress((void**)&logits_p,  g_logits);

    const int M_qs = Bc*Wc*Sc;   // 20480
    const int M_st = Bc*Wc*Nc;   // 8192

    cudaFuncSetAttribute(fused_kernel,
        cudaFuncAttributeMaxDynamicSharedMemorySize, SM_TOT * 4);

    qslot_kernel<<<Bc*Wc, 256>>>(h, c, pos, qslot_p);
    gemm128_kernel<<<M_qs/32, 256>>>(qslot_p, wgt, nullptr, qw_p, M_qs);
    gemm128_kernel<<<M_qs/32, 256>>>(qslot_p, W1, b1, qslotw1_p, M_qs);
    gemm128_kernel<<<M_st/32, 256>>>(qst, W1 + 128*128, nullptr, qsw_p, M_st);

    fused_kernel<<<Bc*Wc, 512, SM_TOT * 4>>>(
        qw_p, qslotw1_p, qst, qsw_p, W2, b2, W3, b3, logits_p);

    int scalar_idx = (out_size == 2*Bc*Sc*Nc + 1) ? Bc*Sc*Nc : -1;
    int logits_off = out_size - Bc*Sc*Nc;
    finalize_kernel<<<Bc, 160>>>(logits_p, mask, out, scalar_idx, logits_off);
}